// round 10
// baseline (speedup 1.0000x reference)
#include <cuda_runtime.h>
#include <cuda_fp16.h>
#include <stdint.h>

// INT2 symmetric quantized linear: y[32,14336] = x[32,4096] @ W^T
//   W[o][k] = fp16(v[o][k]-2) * scale[o/128][k]  (exact in fp16: v-2 in {-2,-1,0,1})
// => y[m][o] = sum_k fp16(x[m][k]*scale[g][k]) * (v[o][k]-2)   (scale folded into A)
//
// Harness dtype model: {float32, int32, bfloat16} only. So:
//   scale (jnp.float16) arrives as float32 [112*4096]
//   packed_weight (jnp.uint8) arrives as int32 [14680064], one packed byte per element
// mma.sync.m16n8k16 f16/f32, ldmatrix for A, integer-convert dequant for B.
// 112 CTAs (one weight group each), 256 threads = 8 warps, warp w owns 16 output cols.

#define IN_F   4096
#define OUT_F  14336
#define GS     128
#define NGROUPS 112
#define CK     512                 // K per chunk
#define NCH    (IN_F / CK)         // 8 chunks
#define KSTEPS (CK / 16)           // 32 k16 steps per chunk

#define PK_STRIDE 144              // staged packed row stride (128B data + pad)
#define XS_STRIDE 1040             // staged A row stride (1024B data + pad)
#define PKBUF (128 * PK_STRIDE)    // 18432
#define XSBUF (32 * XS_STRIDE)     // 33280

#define SM_SCALE 0                           // 16384 B (group scales, fp32)
#define SM_PK    16384                       // 2 * PKBUF = 36864
#define SM_XS    (SM_PK + 2 * PKBUF)         // 53248 ; 2 * XSBUF = 66560
#define SM_TOTAL (SM_XS + 2 * XSBUF)         // 119808

__device__ __forceinline__ uint32_t smem_u32(const void* p) {
    uint32_t a;
    asm("{ .reg .u64 t; cvta.to.shared.u64 t, %1; cvt.u32.u64 %0, t; }" : "=r"(a) : "l"(p));
    return a;
}

// nib = two 2-bit weights (pre-masked). fp16x2 of (v0-2, v1-2) via integer converts.
__device__ __forceinline__ uint32_t deq_nib(uint32_t nib) {
    int v0 = (int)(nib & 3u) - 2;
    int v1 = (int)((nib >> 2) & 3u) - 2;
    __half2 h = __halves2half2(__int2half_rn(v0), __int2half_rn(v1));
    return *reinterpret_cast<uint32_t*>(&h);
}

// pack low bytes of 4 int32 into one word (little-endian byte order)
__device__ __forceinline__ uint32_t pack4(uint4 q) {
    return __byte_perm(__byte_perm(q.x, q.y, 0x0040),
                       __byte_perm(q.z, q.w, 0x0040), 0x5410);
}

#define LDSM_X4(R, ADDR) \
    asm volatile("ldmatrix.sync.aligned.m8n8.x4.shared.b16 {%0,%1,%2,%3}, [%4];" \
        : "=r"((R)[0]), "=r"((R)[1]), "=r"((R)[2]), "=r"((R)[3]) : "r"(ADDR))

#define MMA16816(C, A, B0, B1) \
    asm volatile("mma.sync.aligned.m16n8k16.row.col.f32.f16.f16.f32 " \
        "{%0,%1,%2,%3}, {%4,%5,%6,%7}, {%8,%9}, {%0,%1,%2,%3};" \
        : "+f"((C)[0]), "+f"((C)[1]), "+f"((C)[2]), "+f"((C)[3]) \
        : "r"((A)[0]), "r"((A)[1]), "r"((A)[2]), "r"((A)[3]), "r"(B0), "r"(B1))

#define STS128(ADDR, R0, R1, R2, R3) \
    asm volatile("st.shared.v4.b32 [%0], {%1, %2, %3, %4};" \
        :: "r"(ADDR), "r"(R0), "r"(R1), "r"(R2), "r"(R3) : "memory")

#define LDS128F(ADDR, V) \
    asm volatile("ld.shared.v4.f32 {%0,%1,%2,%3}, [%4];" \
        : "=f"((V).x), "=f"((V).y), "=f"((V).z), "=f"((V).w) : "r"(ADDR))

__global__ void __launch_bounds__(256, 1)
int2_linear_kernel(const float* __restrict__ x,
                   const int* __restrict__ pw,     // one packed byte per int32
                   const float* __restrict__ scale,
                   float* __restrict__ out)
{
    extern __shared__ char smem[];
    const int tid  = threadIdx.x;
    const int warp = tid >> 5;
    const int lane = tid & 31;
    const int g    = blockIdx.x;
    const uint32_t sbase = smem_u32(smem);

    // ---- stage group scales: 4096 fp32 = 16KB ----
    {
        const uint4* sg = reinterpret_cast<const uint4*>(scale + (size_t)g * IN_F);
        uint4* ss = reinterpret_cast<uint4*>(smem + SM_SCALE);
#pragma unroll
        for (int i = 0; i < 4; ++i) ss[tid + i * 256] = sg[tid + i * 256];
    }

    const int* pwg = pw + (size_t)g * GS * (IN_F / 4);   // 1024 int32 per row
    const int prow = tid >> 1, phalf = tid & 1;          // pw staging: half-row per thread

    // ---- pw prefetch (64 consecutive int32 = 256B contiguous per thread) ----
    uint4 R[16];
#define PW_LDG(CH) do {                                                        \
    const uint4* src = reinterpret_cast<const uint4*>(                         \
        pwg + (size_t)prow * (IN_F / 4) + (CH) * (CK / 4) + phalf * 64);       \
    _Pragma("unroll")                                                          \
    for (int u = 0; u < 16; ++u) R[u] = src[u];                                \
} while (0)

#define PW_STS(BUF) do {                                                       \
    uint32_t base = sbase + SM_PK + (BUF) * PKBUF + prow * PK_STRIDE + phalf * 64; \
    _Pragma("unroll")                                                          \
    for (int t = 0; t < 4; ++t) {                                              \
        uint32_t w0 = pack4(R[4 * t + 0]), w1 = pack4(R[4 * t + 1]);           \
        uint32_t w2 = pack4(R[4 * t + 2]), w3 = pack4(R[4 * t + 3]);           \
        STS128(base + t * 16, w0, w1, w2, w3);                                 \
    }                                                                          \
} while (0)

    // ---- xs compute (fills xs[buf] with fp16(x*scale) for chunk cc) ----
    const int xrow = tid >> 3, xp = tid & 7;          // 32 rows x 8 col-segments
#define COMPUTE_XS(BUF, CC) do {                                               \
    const float* xg = x + (size_t)xrow * IN_F + (CC) * CK + xp * 8;            \
    uint32_t sa = sbase + SM_SCALE + (uint32_t)(((CC) * CK + xp * 8) * 4);     \
    uint32_t xa = sbase + SM_XS + (BUF) * XSBUF + xrow * XS_STRIDE + xp * 16;  \
    _Pragma("unroll")                                                          \
    for (int i = 0; i < 8; ++i) {                                              \
        float4 v0 = *reinterpret_cast<const float4*>(xg + i * 64);             \
        float4 v1 = *reinterpret_cast<const float4*>(xg + i * 64 + 4);         \
        float4 s0, s1;                                                         \
        LDS128F(sa + i * 256, s0);                                             \
        LDS128F(sa + i * 256 + 16, s1);                                        \
        __half2 h0 = __floats2half2_rn(v0.x * s0.x, v0.y * s0.y);              \
        __half2 h1 = __floats2half2_rn(v0.z * s0.z, v0.w * s0.w);              \
        __half2 h2 = __floats2half2_rn(v1.x * s1.x, v1.y * s1.y);              \
        __half2 h3 = __floats2half2_rn(v1.z * s1.z, v1.w * s1.w);              \
        STS128(xa + i * 128,                                                   \
               *reinterpret_cast<uint32_t*>(&h0),                              \
               *reinterpret_cast<uint32_t*>(&h1),                              \
               *reinterpret_cast<uint32_t*>(&h2),                              \
               *reinterpret_cast<uint32_t*>(&h3));                             \
    }                                                                          \
} while (0)

    __syncthreads();            // scales visible
    PW_LDG(0);
    COMPUTE_XS(0, 0);
    PW_STS(0);
    __syncthreads();            // xs0 + pk0 ready

    // ---- per-warp fragment addressing ----
    const int nbase = warp * 16;
    const int q = lane & 3;
    const uint32_t sh0 = q * 4;                       // bit shift for k-pair 2q
    const uint32_t pkoff0 = (uint32_t)((nbase + (lane >> 2)) * PK_STRIDE);
    const uint32_t pkoff1 = pkoff0 + 8 * PK_STRIDE;
    const int arow = (lane & 7) + ((lane >> 3) & 1) * 8;
    const uint32_t acol = ((lane >> 4) & 1) * 16;
    const uint32_t am0off = (uint32_t)(arow * XS_STRIDE) + acol;

    float c[2][2][4] = {};

    for (int ch = 0; ch < NCH; ++ch) {
        const int cb = ch & 1, nb = cb ^ 1;

        if (ch + 1 < NCH) PW_LDG(ch + 1);   // LDG latency hidden under the mma loop

        const uint32_t pkb0 = sbase + SM_PK + cb * PKBUF + pkoff0;
        const uint32_t pkb1 = sbase + SM_PK + cb * PKBUF + pkoff1;
        const uint32_t am0  = sbase + SM_XS + cb * XSBUF + am0off;
        const uint32_t am1  = am0 + 16 * XS_STRIDE;

#pragma unroll 8
        for (int j = 0; j < KSTEPS; ++j) {
            uint32_t w0, w1;
            asm volatile("ld.shared.u32 %0, [%1];" : "=r"(w0) : "r"(pkb0 + j * 4));
            asm volatile("ld.shared.u32 %0, [%1];" : "=r"(w1) : "r"(pkb1 + j * 4));
            uint32_t a0[4], a1[4];
            LDSM_X4(a0, am0 + j * 32);
            LDSM_X4(a1, am1 + j * 32);

            uint32_t t0 = w0 >> sh0;
            uint32_t b00 = deq_nib(t0 & 0xFu);          // k = 2q, 2q+1
            uint32_t b01 = deq_nib((t0 >> 16) & 0xFu);  // k = 2q+8, 2q+9
            uint32_t t1 = w1 >> sh0;
            uint32_t b10 = deq_nib(t1 & 0xFu);
            uint32_t b11 = deq_nib((t1 >> 16) & 0xFu);

            MMA16816(c[0][0], a0, b00, b01);
            MMA16816(c[1][0], a1, b00, b01);
            MMA16816(c[0][1], a0, b10, b11);
            MMA16816(c[1][1], a1, b10, b11);
        }

        if (ch + 1 < NCH) {
            COMPUTE_XS(nb, ch + 1);
            PW_STS(nb);
        }
        __syncthreads();
    }

    // ---- epilogue: write C fragments ----
#pragma unroll
    for (int mt = 0; mt < 2; ++mt) {
#pragma unroll
        for (int nt = 0; nt < 2; ++nt) {
            const int m0  = mt * 16 + (lane >> 2);
            const int col = g * GS + nbase + nt * 8 + q * 2;
            float2 lo = make_float2(c[mt][nt][0], c[mt][nt][1]);
            float2 hi = make_float2(c[mt][nt][2], c[mt][nt][3]);
            *reinterpret_cast<float2*>(out + (size_t)m0 * OUT_F + col) = lo;
            *reinterpret_cast<float2*>(out + (size_t)(m0 + 8) * OUT_F + col) = hi;
        }
    }
}

extern "C" void kernel_launch(void* const* d_in, const int* in_sizes, int n_in,
                              void* d_out, int out_size) {
    // Identify inputs by element count (dtype-independent):
    //   x: 131072 ; packed: 14680064 ; scale: 458752
    const float* x  = 0;
    const int*   pw = 0;
    const float* sc = 0;
    for (int i = 0; i < n_in; ++i) {
        if      (in_sizes[i] == 131072)   x  = (const float*)d_in[i];
        else if (in_sizes[i] == 14680064) pw = (const int*)d_in[i];
        else if (in_sizes[i] == 458752)   sc = (const float*)d_in[i];
    }
    float* out = (float*)d_out;
    (void)out_size;

    cudaFuncSetAttribute(int2_linear_kernel,
                         cudaFuncAttributeMaxDynamicSharedMemorySize, SM_TOTAL);
    int2_linear_kernel<<<NGROUPS, 256, SM_TOTAL>>>(x, pw, sc, out);
}